// round 16
// baseline (speedup 1.0000x reference)
#include <cuda_runtime.h>
#include <cuda_bf16.h>
#include <cuda_fp16.h>
#include <math.h>
#include <stdint.h>

// B=1024, S=32, D=1024, D2=2048
// 5-launch pipeline: k_prep -> k_gs (gemmM|skinny) -> k_mid (Mred|skred|small)
//                    -> k_yzrag (yz 128x128 3-stage, 2CTA/SM | rag 3-stage) -> k_attn2

// ----- static scratch -----
__device__ float g_Cq[65536], g_Ck[65536], g_Cv[65536];
__device__ float g_A[32768], g_Bm[32768], g_G[32768];
__device__ float g_part[786432];     // [3][8][32][1024]
__device__ float g_c[1024], g_P[1024];
__device__ float g_Zpart[8388608];   // gemmM split-K partials (4x1M), then Z [8][1024][32][32]
__device__ float g_RAG[2097152];     // [64][32768]
__device__ __align__(16) __half g_Xh[33554432];
__device__ __align__(16) __half g_MhT[1048576];
__device__ __align__(16) __half g_AGh[65536];
__device__ __align__(16) __half g_AGl[65536];
__device__ __align__(16) __nv_bfloat16 g_WqTh[2097152];
__device__ __align__(16) __nv_bfloat16 g_WqTl[2097152];
__device__ __align__(16) __nv_bfloat16 g_WkTh[2097152];
__device__ __align__(16) __nv_bfloat16 g_WkTl[2097152];
__device__ __align__(16) __nv_bfloat16 g_WvTh[2097152];
__device__ __align__(16) __nv_bfloat16 g_WvTl[2097152];
__device__ __align__(16) __nv_bfloat16 g_CqH[65536], g_CqL[65536];
__device__ __align__(16) __nv_bfloat16 g_CkH[65536], g_CkL[65536];
__device__ __align__(16) __nv_bfloat16 g_WfH[65536], g_WfL[65536];

__device__ __forceinline__ float wredsum(float v) {
#pragma unroll
    for (int o = 16; o; o >>= 1) v += __shfl_xor_sync(0xffffffffu, v, o);
    return v;
}
__device__ __forceinline__ float wredmax(float v) {
#pragma unroll
    for (int o = 16; o; o >>= 1) v = fmaxf(v, __shfl_xor_sync(0xffffffffu, v, o));
    return v;
}
__device__ __forceinline__ uint32_t smem_u32(const void* p) {
    uint32_t a;
    asm("{ .reg .u64 t; cvta.to.shared.u64 t, %1; cvt.u32.u64 %0, t; }" : "=r"(a) : "l"(p));
    return a;
}
__device__ __forceinline__ void ldsm4(uint32_t* r, uint32_t addr) {
    asm volatile("ldmatrix.sync.aligned.m8n8.x4.shared.b16 {%0,%1,%2,%3}, [%4];"
                 : "=r"(r[0]), "=r"(r[1]), "=r"(r[2]), "=r"(r[3]) : "r"(addr));
}
__device__ __forceinline__ void mma_bf16(float* d, const uint32_t* a,
                                         uint32_t b0, uint32_t b1) {
    asm volatile(
        "mma.sync.aligned.m16n8k16.row.col.f32.bf16.bf16.f32 "
        "{%0,%1,%2,%3}, {%4,%5,%6,%7}, {%8,%9}, {%0,%1,%2,%3};"
        : "+f"(d[0]), "+f"(d[1]), "+f"(d[2]), "+f"(d[3])
        : "r"(a[0]), "r"(a[1]), "r"(a[2]), "r"(a[3]), "r"(b0), "r"(b1));
}
__device__ __forceinline__ void mma_f16(float* d, const uint32_t* a,
                                        uint32_t b0, uint32_t b1) {
    asm volatile(
        "mma.sync.aligned.m16n8k16.row.col.f32.f16.f16.f32 "
        "{%0,%1,%2,%3}, {%4,%5,%6,%7}, {%8,%9}, {%0,%1,%2,%3};"
        : "+f"(d[0]), "+f"(d[1]), "+f"(d[2]), "+f"(d[3])
        : "r"(a[0]), "r"(a[1]), "r"(a[2]), "r"(a[3]), "r"(b0), "r"(b1));
}
__device__ __forceinline__ void cpasync16(uint32_t saddr, const void* gaddr) {
    asm volatile("cp.async.cg.shared.global [%0], [%1], 16;" :: "r"(saddr), "l"(gaddr));
}
#define CP_COMMIT() asm volatile("cp.async.commit_group;" ::: "memory")
#define CP_WAIT(n)  asm volatile("cp.async.wait_group %0;" :: "n"(n) : "memory")

// ===== merged prep =====
__global__ __launch_bounds__(256) void k_prep(const float* __restrict__ x,
                                              const float* __restrict__ pe,
                                              const float* __restrict__ Wq, const float* __restrict__ bq,
                                              const float* __restrict__ Wk, const float* __restrict__ bk,
                                              const float* __restrict__ Wv, const float* __restrict__ bv,
                                              const float* __restrict__ Wfc) {
    __shared__ float sh[32 * 33];
    int blk = blockIdx.x;
    int tid = threadIdx.x;
    if (blk < 768) {
        int bz = blk >> 8, bx = blk & 255;
        const float* W; const float* bias; float* out;
        if (bz == 0)      { W = Wq; bias = bq; out = g_Cq; }
        else if (bz == 1) { W = Wk; bias = bk; out = g_Ck; }
        else              { W = Wv; bias = bv; out = g_Cv; }
        int warp = tid >> 5, lane = tid & 31;
        int d2 = bx * 8 + warp;
        float acc[32];
#pragma unroll
        for (int i = 0; i < 32; i++) acc[i] = 0.f;
        for (int e0 = 0; e0 < 1024; e0 += 32) {
            __syncthreads();
#pragma unroll
            for (int p = 0; p < 4; p++) {
                int idx = p * 256 + tid;
                sh[(idx >> 5) * 33 + (idx & 31)] = pe[(idx >> 5) * 1024 + e0 + (idx & 31)];
            }
            __syncthreads();
            float wv = W[(size_t)d2 * 2048 + 1024 + e0 + lane];
#pragma unroll
            for (int i = 0; i < 32; i++) acc[i] += sh[i * 33 + lane] * wv;
        }
        float res = 0.f;
#pragma unroll
        for (int i = 0; i < 32; i++) {
            float r = wredsum(acc[i]);
            if (lane == i) res = r;
        }
        float val = res + bias[d2];
        out[lane * 2048 + d2] = val;
        if (bz < 2) {
            __nv_bfloat16 h = __float2bfloat16(val);
            __nv_bfloat16 l = __float2bfloat16(val - __bfloat162float(h));
            __nv_bfloat16* oh = bz ? g_CkH : g_CqH;
            __nv_bfloat16* ol = bz ? g_CkL : g_CqL;
            oh[lane * 2048 + d2] = h;
            ol[lane * 2048 + d2] = l;
        }
    } else if (blk < 6912) {
        int b2 = blk - 768;
        int bx = b2 & 31, by = (b2 >> 5) & 63, bz = b2 >> 11;
        const float* W = (bz == 0) ? Wq : (bz == 1) ? Wk : Wv;
        __nv_bfloat16* oh = (bz == 0) ? g_WqTh : (bz == 1) ? g_WkTh : g_WvTh;
        __nv_bfloat16* ol = (bz == 0) ? g_WqTl : (bz == 1) ? g_WkTl : g_WvTl;
        int xx = tid & 31, yy = tid >> 5;
#pragma unroll
        for (int i = 0; i < 32; i += 8)
            sh[(yy + i) * 33 + xx] = W[(size_t)(by * 32 + yy + i) * 2048 + bx * 32 + xx];
        __syncthreads();
#pragma unroll
        for (int i = 0; i < 32; i += 8) {
            float v = sh[xx * 33 + yy + i];
            __nv_bfloat16 h = __float2bfloat16(v);
            __nv_bfloat16 l = __float2bfloat16(v - __bfloat162float(h));
            size_t o = (size_t)(bx * 32 + yy + i) * 2048 + by * 32 + xx;
            oh[o] = h;
            ol[o] = l;
        }
    } else if (blk < 6976) {
        int idx4 = (blk - 6912) * 256 + tid;
        float4 v = *(const float4*)(Wfc + (size_t)idx4 * 4);
        float vv[4] = {v.x, v.y, v.z, v.w};
#pragma unroll
        for (int q = 0; q < 4; q++) {
            __nv_bfloat16 h = __float2bfloat16(vv[q]);
            g_WfH[idx4 * 4 + q] = h;
            g_WfL[idx4 * 4 + q] = __float2bfloat16(vv[q] - __bfloat162float(h));
        }
    } else {
        size_t i = ((size_t)(blk - 6976) * 256 + tid) * 4;
        float4 v = *(const float4*)(x + i);
        *(__half2*)(g_Xh + i)     = __halves2half2(__float2half_rn(v.x), __float2half_rn(v.y));
        *(__half2*)(g_Xh + i + 2) = __halves2half2(__float2half_rn(v.z), __float2half_rn(v.w));
    }
}

// ===== k_gs: merged gemmM (blk<256) | skinny (blk 256..447) =====
#define GPAD 72
#define GBUF (128 * GPAD * 2)
#define GSTAGE (4 * GBUF)        // 73728
#define GSMEM (3 * GSTAGE)       // 221184
#define SK_AB (32 * 72 * 2)
#define SK_BB (128 * 72 * 2)
#define SKSTAGE (2 * SK_AB + 2 * SK_BB)   // 46080

__device__ __forceinline__ void g_stage(uint32_t sb, int s, int m0, int n0,
                                        int k0, int tid) {
    uint32_t sa = sb + s * GSTAGE;
#pragma unroll
    for (int p = 0; p < 16; p++) {
        int idx = p * 256 + tid;
        int buf = idx >> 10;
        int t = idx & 1023;
        int row = t >> 3, c = t & 7;
        const __nv_bfloat16* src =
            (buf == 0) ? g_WqTh : (buf == 1) ? g_WqTl : (buf == 2) ? g_WkTh : g_WkTl;
        int r0 = (buf < 2) ? m0 : n0;
        cpasync16(sa + buf * GBUF + (uint32_t)(row * GPAD + c * 8) * 2,
                  src + (size_t)(r0 + row) * 2048 + k0 + c * 8);
    }
}

__device__ __forceinline__ void sk_stage256(uint32_t sb, int s,
                                            const __nv_bfloat16* __restrict__ Ah,
                                            const __nv_bfloat16* __restrict__ Al,
                                            const __nv_bfloat16* __restrict__ Bh,
                                            const __nv_bfloat16* __restrict__ Bl,
                                            int n0, int k0, int tid) {
    uint32_t sa = sb + s * SKSTAGE;
#pragma unroll
    for (int p = 0; p < 2; p++) {
        int idx = p * 256 + tid;
        int bufl = idx >> 8;
        int t = idx & 255;
        int row = t >> 3, ch = t & 7;
        const __nv_bfloat16* src = bufl ? Al : Ah;
        cpasync16(sa + bufl * SK_AB + (uint32_t)(row * 72 + ch * 8) * 2,
                  src + (size_t)row * 2048 + k0 + ch * 8);
    }
#pragma unroll
    for (int p = 0; p < 8; p++) {
        int idx = p * 256 + tid;
        int bufl = idx >> 10;
        int t = idx & 1023;
        int row = t >> 3, ch = t & 7;
        const __nv_bfloat16* src = bufl ? Bl : Bh;
        cpasync16(sa + 2 * SK_AB + bufl * SK_BB + (uint32_t)(row * 72 + ch * 8) * 2,
                  src + (size_t)(n0 + row) * 2048 + k0 + ch * 8);
    }
}

__global__ __launch_bounds__(256, 1) void k_gs() {
    extern __shared__ __align__(16) char gsmem[];
    const uint32_t sb = smem_u32(gsmem);
    const int tid = threadIdx.x, lane = tid & 31, wid = tid >> 5;
    int blk = blockIdx.x;
    if (blk < 256) {
        const int wm = wid >> 2, wn = wid & 3;
        const int m0 = ((blk >> 3) & 7) * 128, n0 = (blk & 7) * 128;
        const int kbase = (blk >> 6) * 512;

        g_stage(sb, 0, m0, n0, kbase, tid);
        CP_COMMIT();
        g_stage(sb, 1, m0, n0, kbase + 64, tid);
        CP_COMMIT();

        float d[4][4][4] = {};
        const int aRow = wm * 64 + (lane & 15);
        const int aCol = (lane >> 4) * 8;
        const int bRow = wn * 32 + (lane & 7) + (lane >> 4) * 8;
        const int bCol = ((lane >> 3) & 1) * 8;

        for (int it = 0; it < 8; it++) {
            if (it < 7) CP_WAIT(1); else CP_WAIT(0);
            __syncthreads();
            if (it + 2 < 8) {
                g_stage(sb, (it + 2) % 3, m0, n0, kbase + (it + 2) * 64, tid);
                CP_COMMIT();
            }
            uint32_t st = sb + (it % 3) * GSTAGE;
#pragma unroll
            for (int ks = 0; ks < 4; ks++) {
                int kc = ks * 16;
                uint32_t arh[4][4], arl[4][4];
#pragma unroll
                for (int i = 0; i < 4; i++) {
                    uint32_t ao = (uint32_t)((aRow + i * 16) * GPAD + kc + aCol) * 2;
                    ldsm4(arh[i], st + ao);
                    ldsm4(arl[i], st + GBUF + ao);
                }
                uint32_t brh[2][4], brl[2][4];
#pragma unroll
                for (int j = 0; j < 2; j++) {
                    uint32_t bo = (uint32_t)((bRow + j * 16) * GPAD + kc + bCol) * 2;
                    ldsm4(brh[j], st + 2 * GBUF + bo);
                    ldsm4(brl[j], st + 3 * GBUF + bo);
                }
#pragma unroll
                for (int i = 0; i < 4; i++)
#pragma unroll
                    for (int j = 0; j < 4; j++) {
                        uint32_t h0 = brh[j >> 1][(j & 1) * 2], h1 = brh[j >> 1][(j & 1) * 2 + 1];
                        uint32_t l0 = brl[j >> 1][(j & 1) * 2], l1 = brl[j >> 1][(j & 1) * 2 + 1];
                        mma_bf16(d[i][j], arh[i], h0, h1);
                        mma_bf16(d[i][j], arh[i], l0, l1);
                        mma_bf16(d[i][j], arl[i], h0, h1);
                    }
            }
        }
        float* outp = g_Zpart + (size_t)(blk >> 6) * 1048576;
        const int grp = lane >> 2, tig = lane & 3;
        const int mb = m0 + wm * 64, nb = n0 + wn * 32;
#pragma unroll
        for (int i = 0; i < 4; i++) {
            int r0 = mb + i * 16 + grp, r1 = r0 + 8;
#pragma unroll
            for (int j = 0; j < 4; j++) {
                int cc = nb + j * 8 + tig * 2;
                *(float2*)(outp + (size_t)r0 * 1024 + cc) = make_float2(d[i][j][0], d[i][j][1]);
                *(float2*)(outp + (size_t)r1 * 1024 + cc) = make_float2(d[i][j][2], d[i][j][3]);
            }
        }
    } else {
        int s2 = blk - 256;
        const int z = s2 >> 6;
        const int n0 = (s2 & 7) * 128;
        const int kbase = ((s2 >> 3) & 7) * 256;

        const __nv_bfloat16* Ah = (z == 0) ? g_CkH : (z == 1) ? g_CqH : g_WfH;
        const __nv_bfloat16* Al = (z == 0) ? g_CkL : (z == 1) ? g_CqL : g_WfL;
        const __nv_bfloat16* Bh = (z == 0) ? g_WqTh : (z == 1) ? g_WkTh : g_WvTh;
        const __nv_bfloat16* Bl = (z == 0) ? g_WqTl : (z == 1) ? g_WkTl : g_WvTl;

        sk_stage256(sb, 0, Ah, Al, Bh, Bl, n0, kbase, tid);
        CP_COMMIT();

        float d[2][2][2][4] = {};
        const int wn = wid;
        const int aRow = lane & 15;
        const int aCol = (lane >> 4) * 8;
        const int bRow = (wn & 3) * 32 + (lane & 7) + (lane >> 4) * 8;
        const int bCol = ((lane >> 3) & 1) * 8;

        for (int it = 0; it < 4; it++) {
            CP_WAIT(0);
            __syncthreads();
            if (it + 1 < 4) {
                sk_stage256(sb, (it + 1) & 1, Ah, Al, Bh, Bl, n0, kbase + (it + 1) * 64, tid);
                CP_COMMIT();
            }
            if (wid < 4) {
                uint32_t st = sb + (it & 1) * SKSTAGE;
                uint32_t sB = st + 2 * SK_AB;
#pragma unroll
                for (int ks = 0; ks < 4; ks++) {
                    int kc = ks * 16;
                    uint32_t ah[2][4], al[2][4];
#pragma unroll
                    for (int mi = 0; mi < 2; mi++) {
                        uint32_t ao = (uint32_t)((mi * 16 + aRow) * 72 + kc + aCol) * 2;
                        ldsm4(ah[mi], st + ao);
                        ldsm4(al[mi], st + SK_AB + ao);
                    }
                    uint32_t bh[2][4], bl[2][4];
#pragma unroll
                    for (int nj = 0; nj < 2; nj++) {
                        uint32_t bo = (uint32_t)((bRow + nj * 16) * 72 + kc + bCol) * 2;
                        ldsm4(bh[nj], sB + bo);
                        ldsm4(bl[nj], sB + SK_BB + bo);
                    }
#pragma unroll
                    for (int mi = 0; mi < 2; mi++)
#pragma unroll
                        for (int nj = 0; nj < 2; nj++)
#pragma unroll
                            for (int s = 0; s < 2; s++) {
                                mma_bf16(d[mi][nj][s], ah[mi], bh[nj][s * 2], bh[nj][s * 2 + 1]);
                                mma_bf16(d[mi][nj][s], ah[mi], bl[nj][s * 2], bl[nj][s * 2 + 1]);
                                mma_bf16(d[mi][nj][s], al[mi], bh[nj][s * 2], bh[nj][s * 2 + 1]);
                            }
                }
            }
            __syncthreads();
        }
        if (wid < 4) {
            float* outp = g_part + ((size_t)z * 8 + ((s2 >> 3) & 7)) * 32768;
            const int grp = lane >> 2, tig = lane & 3;
#pragma unroll
            for (int mi = 0; mi < 2; mi++) {
                int r0 = mi * 16 + grp, r1 = r0 + 8;
#pragma unroll
                for (int nj = 0; nj < 2; nj++)
#pragma unroll
                    for (int s = 0; s < 2; s++) {
                        int col = n0 + (wn & 3) * 32 + nj * 16 + s * 8 + tig * 2;
                        *(float2*)(outp + r0 * 1024 + col) =
                            make_float2(d[mi][nj][s][0], d[mi][nj][s][1]);
                        *(float2*)(outp + r1 * 1024 + col) =
                            make_float2(d[mi][nj][s][2], d[mi][nj][s][3]);
                    }
            }
        }
    }
}

// ----- k_mid: merged Mred | skred | small -----
__global__ __launch_bounds__(256) void k_mid(const float* __restrict__ Wfc) {
    __shared__ float t[32][33];
    int blk = blockIdx.x, tid = threadIdx.x;
    if (blk < 1024) {
        int bx = blk & 31, by = blk >> 5;
        int x = tid & 31, y = tid >> 5;
#pragma unroll
        for (int i = 0; i < 32; i += 8) {
            size_t o = (size_t)(by * 32 + y + i) * 1024 + bx * 32 + x;
            t[y + i][x] = g_Zpart[o] + g_Zpart[1048576 + o] +
                          g_Zpart[2097152 + o] + g_Zpart[3145728 + o];
        }
        __syncthreads();
#pragma unroll
        for (int i = 0; i < 32; i += 8)
            g_MhT[(size_t)(bx * 32 + y + i) * 1024 + by * 32 + x] = __float2half_rn(t[x][y + i]);
    } else if (blk < 1408) {
        int idx = (blk - 1024) * 256 + tid;
        int z = idx >> 15;
        int r = idx & 32767;
        float s = 0.f;
#pragma unroll
        for (int kc = 0; kc < 8; kc++) s += g_part[((size_t)z * 8 + kc) * 32768 + r];
        float* out = (z == 0) ? g_A : (z == 1) ? g_Bm : g_G;
        out[r] = s;
        if (z != 1) {
            int agrow = (z == 0) ? (r >> 10) : 32 + (r >> 10);
            int col = r & 1023;
            __half h = __float2half_rn(s);
            g_AGh[agrow * 1024 + col] = h;
            g_AGl[agrow * 1024 + col] = __float2half_rn(s - __half2float(h));
        }
    } else {
        int blkr = blk - 1408;
        int i = blkr & 31, by = blkr >> 5;
        const float* L; const float* R; float* out;
        if (by == 0) { L = g_Cq; R = g_Ck; out = g_c; }
        else         { L = Wfc;  R = g_Cv; out = g_P; }
        int warp = tid >> 5, lane = tid & 31;
        float acc[4] = {0.f, 0.f, 0.f, 0.f};
        for (int dd = lane; dd < 2048; dd += 32) {
            float lv = L[i * 2048 + dd];
#pragma unroll
            for (int q = 0; q < 4; q++) acc[q] += lv * R[(warp * 4 + q) * 2048 + dd];
        }
#pragma unroll
        for (int q = 0; q < 4; q++) {
            float r = wredsum(acc[q]);
            if (lane == 0) out[i * 32 + warp * 4 + q] = r;
        }
    }
}

// ====== k_yzrag: yz (blk<2048, 128x128 tile, 3-stage, 2 CTA/SM) | rag (3-stage) ======
#define Y3PAD 72
#define Y3BUF (128 * Y3PAD * 2)            // 18432
#define Y3STAGE (2 * Y3BUF)                // 36864 (A + B)
#define YSMEM3 (3 * Y3STAGE)               // 110592 (>= 3*ZBUF3 = 104448)
#define ZBUF3 (128 * 136 * 2)              // 34816
#define RPAD 72
#define R_A_BYTES (64 * RPAD * 2)          // 9216
#define R_B_BYTES (128 * RPAD * 2)         // 18432
#define RSTAGE (2 * R_A_BYTES + R_B_BYTES) // 36864

__device__ __forceinline__ void y_stage3(uint32_t sb, int s, int m0, int n0,
                                         int k0, int tid) {
    uint32_t sa = sb + s * Y3STAGE;
#pragma unroll
    for (int p = 0; p < 8; p++) {
        int idx = p * 256 + tid;   // 0..2047
        int buf = idx >> 10;
        int t = idx & 1023;        // 128 rows x 8 chunks
        int row = t >> 3, c = t & 7;
        const __half* src = buf ? g_MhT : g_Xh;
        int r0 = buf ? n0 : m0;
        cpasync16(sa + buf * Y3BUF + (uint32_t)(row * Y3PAD + c * 8) * 2,
                  src + (size_t)(r0 + row) * 1024 + k0 + c * 8);
    }
}
__device__ __forceinline__ void r_stage(uint32_t sb, int s, int n0, int k0, int tid) {
    uint32_t sa = sb + s * RSTAGE;
#pragma unroll
    for (int p = 0; p < 4; p++) {
        int idx = p * 256 + tid;
        int bufl = idx >> 9;
        int t = idx & 511;
        int row = t >> 3, ch = t & 7;
        const __half* src = bufl ? g_AGl : g_AGh;
        cpasync16(sa + bufl * R_A_BYTES + (uint32_t)(row * RPAD + ch * 8) * 2,
                  src + (size_t)row * 1024 + k0 + ch * 8);
    }
#pragma unroll
    for (int p = 0; p < 4; p++) {
        int idx = p * 256 + tid;
        int row = idx >> 3, ch = idx & 7;
        cpasync16(sa + 2 * R_A_BYTES + (uint32_t)(row * RPAD + ch * 8) * 2,
                  g_Xh + (size_t)(n0 + row) * 1024 + k0 + ch * 8);
    }
}

__global__ __launch_bounds__(256, 2) void k_yzrag() {
    extern __shared__ __align__(16) char ysmem[];
    const uint32_t sb = smem_u32(ysmem);
    const int tid = threadIdx.x, lane = tid & 31, wid = tid >> 5;
    int blk = blockIdx.x;

    if (blk < 2048) {
        // ---- yz: CTA 128x128, warp tile 64x32, 3-stage ----
        const int wm = wid >> 2, wn = wid & 3;
        const int m0 = (blk >> 3) * 128, n0 = (blk & 7) * 128;

        y_stage3(sb, 0, m0, n0, 0, tid);
        CP_COMMIT();
        y_stage3(sb, 1, m0, n0, 64, tid);
        CP_COMMIT();

        float d[4][4][4] = {};
        const int aRow = wm * 64 + (lane & 15);
        const int aCol = (lane >> 4) * 8;
        const int bRow = wn * 32 + (lane & 7) + (lane >> 4) * 8;
        const int bCol = ((lane >> 3) & 1) * 8;

        for (int it = 0; it < 16; it++) {
            if (it < 15) CP_WAIT(1); else CP_WAIT(0);
            __syncthreads();
            if (it + 2 < 16) {
                y_stage3(sb, (it + 2) % 3, m0, n0, (it + 2) * 64, tid);
                CP_COMMIT();
            }
            uint32_t abase = sb + (it % 3) * Y3STAGE;
            uint32_t bbase = abase + Y3BUF;
#pragma unroll
            for (int ks = 0; ks < 4; ks++) {
                int kc = ks * 16;
                uint32_t ar[4][4];
#pragma unroll
                for (int i = 0; i < 4; i++)
                    ldsm4(ar[i], abase + (uint32_t)((aRow + i * 16) * Y3PAD + kc + aCol) * 2);
                uint32_t br[2][4];
#pragma unroll
                for (int j = 0; j < 2; j++)
                    ldsm4(br[j], bbase + (uint32_t)((bRow + j * 16) * Y3PAD + kc + bCol) * 2);
#pragma unroll
                for (int i = 0; i < 4; i++)
#pragma unroll
                    for (int j = 0; j < 4; j++)
                        mma_f16(d[i][j], ar[i], br[j >> 1][(j & 1) * 2],
                                br[j >> 1][(j & 1) * 2 + 1]);
            }
        }
        __syncthreads();

        // epilogue: add Bm
        const int grp = lane >> 2, tig = lane & 3;
#pragma unroll
        for (int i = 0; i < 4; i++) {
            int r0 = wm * 64 + i * 16 + grp;
            int p0 = r0 & 31, p1 = (r0 + 8) & 31;
#pragma unroll
            for (int j = 0; j < 4; j++) {
                int cc = n0 + wn * 32 + j * 8 + tig * 2;
                float2 b0 = *(const float2*)(g_Bm + p0 * 1024 + cc);
                float2 b1 = *(const float2*)(g_Bm + p1 * 1024 + cc);
                d[i][j][0] += b0.x; d[i][j][1] += b0.y;
                d[i][j][2] += b1.x; d[i][j][3] += b1.y;
            }
        }

        // issue X tile load (128 rows x 128 f-cols at n0), into ZXH
        const uint32_t ZYH = sb, ZYL = sb + ZBUF3, ZXH = sb + 2 * ZBUF3;
#pragma unroll
        for (int p = 0; p < 8; p++) {
            int idx = p * 256 + tid;       // 0..2047 = 128 rows x 16 chunks
            int row = idx >> 4, ch = idx & 15;
            cpasync16(ZXH + (uint32_t)(row * 136 + ch * 8) * 2,
                      g_Xh + (size_t)(m0 + row) * 1024 + n0 + ch * 8);
        }
        CP_COMMIT();
        // write Y' hi/lo (full 128x128, every warp its own cols)
#pragma unroll
        for (int i = 0; i < 4; i++) {
            int r0 = wm * 64 + i * 16 + grp;
#pragma unroll
            for (int j = 0; j < 4; j++) {
                int cl = wn * 32 + j * 8 + tig * 2;
                float v0 = d[i][j][0], v1 = d[i][j][1];
                float v2 = d[i][j][2], v3 = d[i][j][3];
                __half h0 = __float2half_rn(v0), h1 = __float2half_rn(v1);
                __half h2 = __float2half_rn(v2), h3 = __float2half_rn(v3);
                *(__half2*)(ysmem + ((r0) * 136 + cl) * 2) = __halves2half2(h0, h1);
                *(__half2*)(ysmem + ((r0 + 8) * 136 + cl) * 2) = __halves2half2(h2, h3);
                *(__half2*)(ysmem + ZBUF3 + ((r0) * 136 + cl) * 2) =
                    __halves2half2(__float2half_rn(v0 - __half2float(h0)),
                                   __float2half_rn(v1 - __half2float(h1)));
                *(__half2*)(ysmem + ZBUF3 + ((r0 + 8) * 136 + cl) * 2) =
                    __halves2half2(__float2half_rn(v2 - __half2float(h2)),
                                   __float2half_rn(v3 - __half2float(h3)));
            }
        }
        CP_WAIT(0);
        __syncthreads();

        // Z mma: 8 warps = 4 batches x 2 n-halves; k = 128 (this block's f-cols)
        const int bb = wid >> 1;
        const int nh = wid & 1;
        float z[2][2][4] = {};
#pragma unroll
        for (int ksl = 0; ksl < 8; ksl++) {
            int kc = ksl * 16;
            uint32_t ayh[2][4], ayl[2][4];
#pragma unroll
            for (int mi = 0; mi < 2; mi++) {
                uint32_t ao = (uint32_t)((bb * 32 + mi * 16 + (lane & 15)) * 136 +
                                         kc + (lane >> 4) * 8) * 2;
                ldsm4(ayh[mi], ZYH + ao);
                ldsm4(ayl[mi], ZYL + ao);
            }
            uint32_t bxh[4];
            uint32_t bo = (uint32_t)((bb * 32 + nh * 16 + (lane & 7) + (lane >> 4) * 8) * 136 +
                                     kc + ((lane >> 3) & 1) * 8) * 2;
            ldsm4(bxh, ZXH + bo);
#pragma unroll
            for (int mi = 0; mi < 2; mi++)
#pragma unroll
                for (int no = 0; no < 2; no++) {
                    mma_f16(z[mi][no], ayh[mi], bxh[no * 2], bxh[no * 2 + 1]);
                    mma_f16(z[mi][no], ayl[mi], bxh[no * 2], bxh[no * 2 + 1]);
                }
        }
        // store Z partials: slot = n-block (8 slots)
        {
            int b = (blk >> 3) * 4 + bb;
            size_t base = ((size_t)(blk & 7) * 1024 + b) * 1024;
#pragma unroll
            for (int mi = 0; mi < 2; mi++) {
                int i0 = mi * 16 + grp;
#pragma unroll
                for (int no = 0; no < 2; no++) {
                    int j0 = nh * 16 + no * 8 + tig * 2;
                    *(float2*)(g_Zpart + base + i0 * 32 + j0) =
                        make_float2(z[mi][no][0], z[mi][no][1]);
                    *(float2*)(g_Zpart + base + (i0 + 8) * 32 + j0) =
                        make_float2(z[mi][no][2], z[mi][no][3]);
                }
            }
        }
    } else {
        // ---- rag: [A;G] @ Xall^T (2-product), n-tile 128, 3-stage ----
        const int wm = wid >> 2, wn = wid & 3;
        const int n0 = (blk - 2048) * 128;

        r_stage(sb, 0, n0, 0, tid);
        CP_COMMIT();
        r_stage(sb, 1, n0, 64, tid);
        CP_COMMIT();

        float d[2][2][2][4] = {};
        const int aRowB = wm * 32 + (lane & 15);
        const int aCol = (lane >> 4) * 8;
        const int bRowB = wn * 32 + (lane & 7) + (lane >> 4) * 8;
        const int bCol = ((lane >> 3) & 1) * 8;

        for (int it = 0; it < 16; it++) {
            if (it < 15) CP_WAIT(1); else CP_WAIT(0);
            __syncthreads();
            if (it + 2 < 16) {
                r_stage(sb, (it + 2) % 3, n0, (it + 2) * 64, tid);
                CP_COMMIT();
            }
            uint32_t st = sb + (it % 3) * RSTAGE;
            uint32_t sB = st + 2 * R_A_BYTES;
#pragma unroll
            for (int ks = 0; ks < 4; ks++) {
                int kc = ks * 16;
                uint32_t ah[2][4], al[2][4];
#pragma unroll
                for (int mi = 0; mi < 2; mi++) {
                    uint32_t ao = (uint32_t)((aRowB + mi * 16) * RPAD + kc + aCol) * 2;
                    ldsm4(ah[mi], st + ao);
                    ldsm4(al[mi], st + R_A_BYTES + ao);
                }
                uint32_t bh[2][4];
#pragma unroll
                for (int nj = 0; nj < 2; nj++) {
                    uint32_t bo = (uint32_t)((bRowB + nj * 16) * RPAD + kc + bCol) * 2;
                    ldsm4(bh[nj], sB + bo);
                }
#pragma unroll
                for (int mi = 0; mi < 2; mi++)
#pragma unroll
                    for (int nj = 0; nj < 2; nj++)
#pragma unroll
                        for (int s = 0; s < 2; s++) {
                            mma_f16(d[mi][nj][s], ah[mi], bh[nj][s * 2], bh[nj][s * 2 + 1]);
                            mma_f16(d[mi][nj][s], al[mi], bh[nj][s * 2], bh[nj][s * 2 + 1]);
                        }
            }
        }
        const int grp = lane >> 2, tig = lane & 3;
#pragma unroll
        for (int mi = 0; mi < 2; mi++) {
            int r0 = wm * 32 + mi * 16 + grp, r1 = r0 + 8;
#pragma unroll
            for (int nj = 0; nj < 2; nj++)
#pragma unroll
                for (int s = 0; s < 2; s++) {
                    int col = n0 + wn * 32 + nj * 16 + s * 8 + tig * 2;
                    *(float2*)(g_RAG + (size_t)r0 * 32768 + col) =
                        make_float2(d[mi][nj][s][0], d[mi][nj][s][1]);
                    *(float2*)(g_RAG + (size_t)r1 * 32768 + col) =
                        make_float2(d[mi][nj][s][2], d[mi][nj][s][3]);
                }
        }
    }
}

// ----- kernel 7: reduce Z partials (8 slots) + softmax(dim=1) + final dot -----
__global__ __launch_bounds__(256) void k_attn2(const float* __restrict__ bfc,
                                               float* __restrict__ out) {
    __shared__ float Zs[32 * 33];
    __shared__ float As[32 * 33];
    __shared__ float Vs[32 * 33];
    __shared__ float wpart[8];
    int tid = threadIdx.x, b = blockIdx.x;
#pragma unroll
    for (int p = 0; p < 4; p++) {
        int idx = p * 256 + tid;
        int i = idx >> 5, j = idx & 31;
        float s = 0.f;
#pragma unroll
        for (int nb = 0; nb < 8; nb++)
            s += g_Zpart[((size_t)nb * 1024 + b) * 1024 + idx];
        Zs[i * 33 + j] = s;
        As[i * 33 + j] = g_RAG[(size_t)j * 32768 + b * 32 + i];
        Vs[i * 33 + j] = g_RAG[(size_t)(32 + i) * 32768 + b * 32 + j];
    }
    __syncthreads();
    int w = tid >> 5, lane = tid & 31;
    const float rscale = 0.022097086912079608f;  // 1/sqrt(2048)
    float local = 0.f;
#pragma unroll
    for (int q = 0; q < 4; q++) {
        int j = w * 4 + q;
        float lg = (Zs[lane * 33 + j] + As[lane * 33 + j] + g_c[lane * 32 + j]) * rscale;
        float mx = wredmax(lg);
        float ex = __expf(lg - mx);
        float sm = wredsum(ex);
        float contrib = (ex / sm) * (Vs[lane * 33 + j] + g_P[lane * 32 + j]);
        local += wredsum(contrib);
    }
    if (lane == 0) wpart[w] = local;
    __syncthreads();
    if (tid == 0) {
        float t = 0.f;
#pragma unroll
        for (int i = 0; i < 8; i++) t += wpart[i];
        out[b] = t + bfc[0];
    }
}

extern "C" void kernel_launch(void* const* d_in, const int* in_sizes, int n_in,
                              void* d_out, int out_size) {
    const float* x   = (const float*)d_in[0];
    const float* pe  = (const float*)d_in[1];
    const float* Wq  = (const float*)d_in[2];
    const float* bq  = (const float*)d_in[3];
    const float* Wk  = (const float*)d_in[4];
    const float* bk  = (const float*)d_in[5];
    const float* Wv  = (const float*)d_in[6];
    const float* bv  = (const float*)d_in[7];
    const float* Wfc = (const float*)d_in[8];
    const float* bfc = (const float*)d_in[9];
    float* out = (float*)d_out;

    cudaFuncSetAttribute(k_gs, cudaFuncAttributeMaxDynamicSharedMemorySize, GSMEM);
    cudaFuncSetAttribute(k_yzrag, cudaFuncAttributeMaxDynamicSharedMemorySize, YSMEM3);

    k_prep<<<39744, 256>>>(x, pe, Wq, bq, Wk, bk, Wv, bv, Wfc);
    k_gs<<<448, 256, GSMEM>>>();
    k_mid<<<1472, 256>>>(Wfc);
    k_yzrag<<<2304, 256, YSMEM3>>>();
    k_attn2<<<1024, 256>>>(bfc, out);
}

// round 17
// speedup vs baseline: 1.0097x; 1.0097x over previous
#include <cuda_runtime.h>
#include <cuda_bf16.h>
#include <cuda_fp16.h>
#include <math.h>
#include <stdint.h>

// B=1024, S=32, D=1024, D2=2048
// 5-launch pipeline: k_prep -> k_gs (gemmM|skinny) -> k_mid (Mred|skred|small)
//                    -> k_yzrag (rag first | yz 128x128 2-stage, 2CTA/SM) -> k_attn2

// ----- static scratch -----
__device__ float g_Cq[65536], g_Ck[65536], g_Cv[65536];
__device__ float g_A[32768], g_Bm[32768], g_G[32768];
__device__ float g_part[786432];     // [3][8][32][1024]
__device__ float g_c[1024], g_P[1024];
__device__ float g_Zpart[8388608];   // gemmM split-K partials (4x1M), then Z [8][1024][32][32]
__device__ float g_RAG[2097152];     // [64][32768]
__device__ __align__(16) __half g_Xh[33554432];
__device__ __align__(16) __half g_MhT[1048576];
__device__ __align__(16) __half g_AGh[65536];
__device__ __align__(16) __half g_AGl[65536];
__device__ __align__(16) __nv_bfloat16 g_WqTh[2097152];
__device__ __align__(16) __nv_bfloat16 g_WqTl[2097152];
__device__ __align__(16) __nv_bfloat16 g_WkTh[2097152];
__device__ __align__(16) __nv_bfloat16 g_WkTl[2097152];
__device__ __align__(16) __nv_bfloat16 g_WvTh[2097152];
__device__ __align__(16) __nv_bfloat16 g_WvTl[2097152];
__device__ __align__(16) __nv_bfloat16 g_CqH[65536], g_CqL[65536];
__device__ __align__(16) __nv_bfloat16 g_CkH[65536], g_CkL[65536];
__device__ __align__(16) __nv_bfloat16 g_WfH[65536], g_WfL[65536];

__device__ __forceinline__ float wredsum(float v) {
#pragma unroll
    for (int o = 16; o; o >>= 1) v += __shfl_xor_sync(0xffffffffu, v, o);
    return v;
}
__device__ __forceinline__ float wredmax(float v) {
#pragma unroll
    for (int o = 16; o; o >>= 1) v = fmaxf(v, __shfl_xor_sync(0xffffffffu, v, o));
    return v;
}
__device__ __forceinline__ uint32_t smem_u32(const void* p) {
    uint32_t a;
    asm("{ .reg .u64 t; cvta.to.shared.u64 t, %1; cvt.u32.u64 %0, t; }" : "=r"(a) : "l"(p));
    return a;
}
__device__ __forceinline__ void ldsm4(uint32_t* r, uint32_t addr) {
    asm volatile("ldmatrix.sync.aligned.m8n8.x4.shared.b16 {%0,%1,%2,%3}, [%4];"
                 : "=r"(r[0]), "=r"(r[1]), "=r"(r[2]), "=r"(r[3]) : "r"(addr));
}
__device__ __forceinline__ void mma_bf16(float* d, const uint32_t* a,
                                         uint32_t b0, uint32_t b1) {
    asm volatile(
        "mma.sync.aligned.m16n8k16.row.col.f32.bf16.bf16.f32 "
        "{%0,%1,%2,%3}, {%4,%5,%6,%7}, {%8,%9}, {%0,%1,%2,%3};"
        : "+f"(d[0]), "+f"(d[1]), "+f"(d[2]), "+f"(d[3])
        : "r"(a[0]), "r"(a[1]), "r"(a[2]), "r"(a[3]), "r"(b0), "r"(b1));
}
__device__ __forceinline__ void mma_f16(float* d, const uint32_t* a,
                                        uint32_t b0, uint32_t b1) {
    asm volatile(
        "mma.sync.aligned.m16n8k16.row.col.f32.f16.f16.f32 "
        "{%0,%1,%2,%3}, {%4,%5,%6,%7}, {%8,%9}, {%0,%1,%2,%3};"
        : "+f"(d[0]), "+f"(d[1]), "+f"(d[2]), "+f"(d[3])
        : "r"(a[0]), "r"(a[1]), "r"(a[2]), "r"(a[3]), "r"(b0), "r"(b1));
}
__device__ __forceinline__ void cpasync16(uint32_t saddr, const void* gaddr) {
    asm volatile("cp.async.cg.shared.global [%0], [%1], 16;" :: "r"(saddr), "l"(gaddr));
}
#define CP_COMMIT() asm volatile("cp.async.commit_group;" ::: "memory")
#define CP_WAIT(n)  asm volatile("cp.async.wait_group %0;" :: "n"(n) : "memory")

// ===== merged prep =====
__global__ __launch_bounds__(256) void k_prep(const float* __restrict__ x,
                                              const float* __restrict__ pe,
                                              const float* __restrict__ Wq, const float* __restrict__ bq,
                                              const float* __restrict__ Wk, const float* __restrict__ bk,
                                              const float* __restrict__ Wv, const float* __restrict__ bv,
                                              const float* __restrict__ Wfc) {
    __shared__ float sh[32 * 33];
    int blk = blockIdx.x;
    int tid = threadIdx.x;
    if (blk < 768) {
        int bz = blk >> 8, bx = blk & 255;
        const float* W; const float* bias; float* out;
        if (bz == 0)      { W = Wq; bias = bq; out = g_Cq; }
        else if (bz == 1) { W = Wk; bias = bk; out = g_Ck; }
        else              { W = Wv; bias = bv; out = g_Cv; }
        int warp = tid >> 5, lane = tid & 31;
        int d2 = bx * 8 + warp;
        float acc[32];
#pragma unroll
        for (int i = 0; i < 32; i++) acc[i] = 0.f;
        for (int e0 = 0; e0 < 1024; e0 += 32) {
            __syncthreads();
#pragma unroll
            for (int p = 0; p < 4; p++) {
                int idx = p * 256 + tid;
                sh[(idx >> 5) * 33 + (idx & 31)] = pe[(idx >> 5) * 1024 + e0 + (idx & 31)];
            }
            __syncthreads();
            float wv = W[(size_t)d2 * 2048 + 1024 + e0 + lane];
#pragma unroll
            for (int i = 0; i < 32; i++) acc[i] += sh[i * 33 + lane] * wv;
        }
        float res = 0.f;
#pragma unroll
        for (int i = 0; i < 32; i++) {
            float r = wredsum(acc[i]);
            if (lane == i) res = r;
        }
        float val = res + bias[d2];
        out[lane * 2048 + d2] = val;
        if (bz < 2) {
            __nv_bfloat16 h = __float2bfloat16(val);
            __nv_bfloat16 l = __float2bfloat16(val - __bfloat162float(h));
            __nv_bfloat16* oh = bz ? g_CkH : g_CqH;
            __nv_bfloat16* ol = bz ? g_CkL : g_CqL;
            oh[lane * 2048 + d2] = h;
            ol[lane * 2048 + d2] = l;
        }
    } else if (blk < 6912) {
        int b2 = blk - 768;
        int bx = b2 & 31, by = (b2 >> 5) & 63, bz = b2 >> 11;
        const float* W = (bz == 0) ? Wq : (bz == 1) ? Wk : Wv;
        __nv_bfloat16* oh = (bz == 0) ? g_WqTh : (bz == 1) ? g_WkTh : g_WvTh;
        __nv_bfloat16* ol = (bz == 0) ? g_WqTl : (bz == 1) ? g_WkTl : g_WvTl;
        int xx = tid & 31, yy = tid >> 5;
#pragma unroll
        for (int i = 0; i < 32; i += 8)
            sh[(yy + i) * 33 + xx] = W[(size_t)(by * 32 + yy + i) * 2048 + bx * 32 + xx];
        __syncthreads();
#pragma unroll
        for (int i = 0; i < 32; i += 8) {
            float v = sh[xx * 33 + yy + i];
            __nv_bfloat16 h = __float2bfloat16(v);
            __nv_bfloat16 l = __float2bfloat16(v - __bfloat162float(h));
            size_t o = (size_t)(bx * 32 + yy + i) * 2048 + by * 32 + xx;
            oh[o] = h;
            ol[o] = l;
        }
    } else if (blk < 6976) {
        int idx4 = (blk - 6912) * 256 + tid;
        float4 v = *(const float4*)(Wfc + (size_t)idx4 * 4);
        float vv[4] = {v.x, v.y, v.z, v.w};
#pragma unroll
        for (int q = 0; q < 4; q++) {
            __nv_bfloat16 h = __float2bfloat16(vv[q]);
            g_WfH[idx4 * 4 + q] = h;
            g_WfL[idx4 * 4 + q] = __float2bfloat16(vv[q] - __bfloat162float(h));
        }
    } else {
        size_t i = ((size_t)(blk - 6976) * 256 + tid) * 4;
        float4 v = *(const float4*)(x + i);
        *(__half2*)(g_Xh + i)     = __halves2half2(__float2half_rn(v.x), __float2half_rn(v.y));
        *(__half2*)(g_Xh + i + 2) = __halves2half2(__float2half_rn(v.z), __float2half_rn(v.w));
    }
}

// ===== k_gs: merged gemmM (blk<256) | skinny (blk 256..447) =====
#define GPAD 72
#define GBUF (128 * GPAD * 2)
#define GSTAGE (4 * GBUF)        // 73728
#define GSMEM (3 * GSTAGE)       // 221184
#define SK_AB (32 * 72 * 2)
#define SK_BB (128 * 72 * 2)
#define SKSTAGE (2 * SK_AB + 2 * SK_BB)   // 46080

__device__ __forceinline__ void g_stage(uint32_t sb, int s, int m0, int n0,
                                        int k0, int tid) {
    uint32_t sa = sb + s * GSTAGE;
#pragma unroll
    for (int p = 0; p < 16; p++) {
        int idx = p * 256 + tid;
        int buf = idx >> 10;
        int t = idx & 1023;
        int row = t >> 3, c = t & 7;
        const __nv_bfloat16* src =
            (buf == 0) ? g_WqTh : (buf == 1) ? g_WqTl : (buf == 2) ? g_WkTh : g_WkTl;
        int r0 = (buf < 2) ? m0 : n0;
        cpasync16(sa + buf * GBUF + (uint32_t)(row * GPAD + c * 8) * 2,
                  src + (size_t)(r0 + row) * 2048 + k0 + c * 8);
    }
}

__device__ __forceinline__ void sk_stage256(uint32_t sb, int s,
                                            const __nv_bfloat16* __restrict__ Ah,
                                            const __nv_bfloat16* __restrict__ Al,
                                            const __nv_bfloat16* __restrict__ Bh,
                                            const __nv_bfloat16* __restrict__ Bl,
                                            int n0, int k0, int tid) {
    uint32_t sa = sb + s * SKSTAGE;
#pragma unroll
    for (int p = 0; p < 2; p++) {
        int idx = p * 256 + tid;
        int bufl = idx >> 8;
        int t = idx & 255;
        int row = t >> 3, ch = t & 7;
        const __nv_bfloat16* src = bufl ? Al : Ah;
        cpasync16(sa + bufl * SK_AB + (uint32_t)(row * 72 + ch * 8) * 2,
                  src + (size_t)row * 2048 + k0 + ch * 8);
    }
#pragma unroll
    for (int p = 0; p < 8; p++) {
        int idx = p * 256 + tid;
        int bufl = idx >> 10;
        int t = idx & 1023;
        int row = t >> 3, ch = t & 7;
        const __nv_bfloat16* src = bufl ? Bl : Bh;
        cpasync16(sa + 2 * SK_AB + bufl * SK_BB + (uint32_t)(row * 72 + ch * 8) * 2,
                  src + (size_t)(n0 + row) * 2048 + k0 + ch * 8);
    }
}

__global__ __launch_bounds__(256, 1) void k_gs() {
    extern __shared__ __align__(16) char gsmem[];
    const uint32_t sb = smem_u32(gsmem);
    const int tid = threadIdx.x, lane = tid & 31, wid = tid >> 5;
    int blk = blockIdx.x;
    if (blk < 256) {
        const int wm = wid >> 2, wn = wid & 3;
        const int m0 = ((blk >> 3) & 7) * 128, n0 = (blk & 7) * 128;
        const int kbase = (blk >> 6) * 512;

        g_stage(sb, 0, m0, n0, kbase, tid);
        CP_COMMIT();
        g_stage(sb, 1, m0, n0, kbase + 64, tid);
        CP_COMMIT();

        float d[4][4][4] = {};
        const int aRow = wm * 64 + (lane & 15);
        const int aCol = (lane >> 4) * 8;
        const int bRow = wn * 32 + (lane & 7) + (lane >> 4) * 8;
        const int bCol = ((lane >> 3) & 1) * 8;

        for (int it = 0; it < 8; it++) {
            if (it < 7) CP_WAIT(1); else CP_WAIT(0);
            __syncthreads();
            if (it + 2 < 8) {
                g_stage(sb, (it + 2) % 3, m0, n0, kbase + (it + 2) * 64, tid);
                CP_COMMIT();
            }
            uint32_t st = sb + (it % 3) * GSTAGE;
#pragma unroll
            for (int ks = 0; ks < 4; ks++) {
                int kc = ks * 16;
                uint32_t arh[4][4], arl[4][4];
#pragma unroll
                for (int i = 0; i < 4; i++) {
                    uint32_t ao = (uint32_t)((aRow + i * 16) * GPAD + kc + aCol) * 2;
                    ldsm4(arh[i], st + ao);
                    ldsm4(arl[i], st + GBUF + ao);
                }
                uint32_t brh[2][4], brl[2][4];
#pragma unroll
                for (int j = 0; j < 2; j++) {
                    uint32_t bo = (uint32_t)((bRow + j * 16) * GPAD + kc + bCol) * 2;
                    ldsm4(brh[j], st + 2 * GBUF + bo);
                    ldsm4(brl[j], st + 3 * GBUF + bo);
                }
#pragma unroll
                for (int i = 0; i < 4; i++)
#pragma unroll
                    for (int j = 0; j < 4; j++) {
                        uint32_t h0 = brh[j >> 1][(j & 1) * 2], h1 = brh[j >> 1][(j & 1) * 2 + 1];
                        uint32_t l0 = brl[j >> 1][(j & 1) * 2], l1 = brl[j >> 1][(j & 1) * 2 + 1];
                        mma_bf16(d[i][j], arh[i], h0, h1);
                        mma_bf16(d[i][j], arh[i], l0, l1);
                        mma_bf16(d[i][j], arl[i], h0, h1);
                    }
            }
        }
        float* outp = g_Zpart + (size_t)(blk >> 6) * 1048576;
        const int grp = lane >> 2, tig = lane & 3;
        const int mb = m0 + wm * 64, nb = n0 + wn * 32;
#pragma unroll
        for (int i = 0; i < 4; i++) {
            int r0 = mb + i * 16 + grp, r1 = r0 + 8;
#pragma unroll
            for (int j = 0; j < 4; j++) {
                int cc = nb + j * 8 + tig * 2;
                *(float2*)(outp + (size_t)r0 * 1024 + cc) = make_float2(d[i][j][0], d[i][j][1]);
                *(float2*)(outp + (size_t)r1 * 1024 + cc) = make_float2(d[i][j][2], d[i][j][3]);
            }
        }
    } else {
        int s2 = blk - 256;
        const int z = s2 >> 6;
        const int n0 = (s2 & 7) * 128;
        const int kbase = ((s2 >> 3) & 7) * 256;

        const __nv_bfloat16* Ah = (z == 0) ? g_CkH : (z == 1) ? g_CqH : g_WfH;
        const __nv_bfloat16* Al = (z == 0) ? g_CkL : (z == 1) ? g_CqL : g_WfL;
        const __nv_bfloat16* Bh = (z == 0) ? g_WqTh : (z == 1) ? g_WkTh : g_WvTh;
        const __nv_bfloat16* Bl = (z == 0) ? g_WqTl : (z == 1) ? g_WkTl : g_WvTl;

        sk_stage256(sb, 0, Ah, Al, Bh, Bl, n0, kbase, tid);
        CP_COMMIT();

        float d[2][2][2][4] = {};
        const int wn = wid;
        const int aRow = lane & 15;
        const int aCol = (lane >> 4) * 8;
        const int bRow = (wn & 3) * 32 + (lane & 7) + (lane >> 4) * 8;
        const int bCol = ((lane >> 3) & 1) * 8;

        for (int it = 0; it < 4; it++) {
            CP_WAIT(0);
            __syncthreads();
            if (it + 1 < 4) {
                sk_stage256(sb, (it + 1) & 1, Ah, Al, Bh, Bl, n0, kbase + (it + 1) * 64, tid);
                CP_COMMIT();
            }
            if (wid < 4) {
                uint32_t st = sb + (it & 1) * SKSTAGE;
                uint32_t sB = st + 2 * SK_AB;
#pragma unroll
                for (int ks = 0; ks < 4; ks++) {
                    int kc = ks * 16;
                    uint32_t ah[2][4], al[2][4];
#pragma unroll
                    for (int mi = 0; mi < 2; mi++) {
                        uint32_t ao = (uint32_t)((mi * 16 + aRow) * 72 + kc + aCol) * 2;
                        ldsm4(ah[mi], st + ao);
                        ldsm4(al[mi], st + SK_AB + ao);
                    }
                    uint32_t bh[2][4], bl[2][4];
#pragma unroll
                    for (int nj = 0; nj < 2; nj++) {
                        uint32_t bo = (uint32_t)((bRow + nj * 16) * 72 + kc + bCol) * 2;
                        ldsm4(bh[nj], sB + bo);
                        ldsm4(bl[nj], sB + SK_BB + bo);
                    }
#pragma unroll
                    for (int mi = 0; mi < 2; mi++)
#pragma unroll
                        for (int nj = 0; nj < 2; nj++)
#pragma unroll
                            for (int s = 0; s < 2; s++) {
                                mma_bf16(d[mi][nj][s], ah[mi], bh[nj][s * 2], bh[nj][s * 2 + 1]);
                                mma_bf16(d[mi][nj][s], ah[mi], bl[nj][s * 2], bl[nj][s * 2 + 1]);
                                mma_bf16(d[mi][nj][s], al[mi], bh[nj][s * 2], bh[nj][s * 2 + 1]);
                            }
                }
            }
            __syncthreads();
        }
        if (wid < 4) {
            float* outp = g_part + ((size_t)z * 8 + ((s2 >> 3) & 7)) * 32768;
            const int grp = lane >> 2, tig = lane & 3;
#pragma unroll
            for (int mi = 0; mi < 2; mi++) {
                int r0 = mi * 16 + grp, r1 = r0 + 8;
#pragma unroll
                for (int nj = 0; nj < 2; nj++)
#pragma unroll
                    for (int s = 0; s < 2; s++) {
                        int col = n0 + (wn & 3) * 32 + nj * 16 + s * 8 + tig * 2;
                        *(float2*)(outp + r0 * 1024 + col) =
                            make_float2(d[mi][nj][s][0], d[mi][nj][s][1]);
                        *(float2*)(outp + r1 * 1024 + col) =
                            make_float2(d[mi][nj][s][2], d[mi][nj][s][3]);
                    }
            }
        }
    }
}

// ----- k_mid: merged Mred | skred | small -----
__global__ __launch_bounds__(256) void k_mid(const float* __restrict__ Wfc) {
    __shared__ float t[32][33];
    int blk = blockIdx.x, tid = threadIdx.x;
    if (blk < 1024) {
        int bx = blk & 31, by = blk >> 5;
        int x = tid & 31, y = tid >> 5;
#pragma unroll
        for (int i = 0; i < 32; i += 8) {
            size_t o = (size_t)(by * 32 + y + i) * 1024 + bx * 32 + x;
            t[y + i][x] = g_Zpart[o] + g_Zpart[1048576 + o] +
                          g_Zpart[2097152 + o] + g_Zpart[3145728 + o];
        }
        __syncthreads();
#pragma unroll
        for (int i = 0; i < 32; i += 8)
            g_MhT[(size_t)(bx * 32 + y + i) * 1024 + by * 32 + x] = __float2half_rn(t[x][y + i]);
    } else if (blk < 1408) {
        int idx = (blk - 1024) * 256 + tid;
        int z = idx >> 15;
        int r = idx & 32767;
        float s = 0.f;
#pragma unroll
        for (int kc = 0; kc < 8; kc++) s += g_part[((size_t)z * 8 + kc) * 32768 + r];
        float* out = (z == 0) ? g_A : (z == 1) ? g_Bm : g_G;
        out[r] = s;
        if (z != 1) {
            int agrow = (z == 0) ? (r >> 10) : 32 + (r >> 10);
            int col = r & 1023;
            __half h = __float2half_rn(s);
            g_AGh[agrow * 1024 + col] = h;
            g_AGl[agrow * 1024 + col] = __float2half_rn(s - __half2float(h));
        }
    } else {
        int blkr = blk - 1408;
        int i = blkr & 31, by = blkr >> 5;
        const float* L; const float* R; float* out;
        if (by == 0) { L = g_Cq; R = g_Ck; out = g_c; }
        else         { L = Wfc;  R = g_Cv; out = g_P; }
        int warp = tid >> 5, lane = tid & 31;
        float acc[4] = {0.f, 0.f, 0.f, 0.f};
        for (int dd = lane; dd < 2048; dd += 32) {
            float lv = L[i * 2048 + dd];
#pragma unroll
            for (int q = 0; q < 4; q++) acc[q] += lv * R[(warp * 4 + q) * 2048 + dd];
        }
#pragma unroll
        for (int q = 0; q < 4; q++) {
            float r = wredsum(acc[q]);
            if (lane == 0) out[i * 32 + warp * 4 + q] = r;
        }
    }
}

// ====== k_yzrag: rag FIRST (blk<256) | yz (blk 256..2303, 128x128, 2-stage, 2 CTA/SM) ======
#define Y3PAD 72
#define Y3BUF (128 * Y3PAD * 2)            // 18432
#define Y3STAGE (2 * Y3BUF)                // 36864 (A + B)
#define ZBUF3 (128 * 136 * 2)              // 34816
#define YSMEM3 (3 * ZBUF3)                 // 104448 (>= 2*Y3STAGE = 73728)
#define RPAD 72
#define R_A_BYTES (64 * RPAD * 2)          // 9216
#define R_B_BYTES (128 * RPAD * 2)         // 18432
#define RSTAGE (2 * R_A_BYTES + R_B_BYTES) // 36864

__device__ __forceinline__ void y_stage3(uint32_t sb, int s, int m0, int n0,
                                         int k0, int tid) {
    uint32_t sa = sb + s * Y3STAGE;
#pragma unroll
    for (int p = 0; p < 8; p++) {
        int idx = p * 256 + tid;   // 0..2047
        int buf = idx >> 10;
        int t = idx & 1023;        // 128 rows x 8 chunks
        int row = t >> 3, c = t & 7;
        const __half* src = buf ? g_MhT : g_Xh;
        int r0 = buf ? n0 : m0;
        cpasync16(sa + buf * Y3BUF + (uint32_t)(row * Y3PAD + c * 8) * 2,
                  src + (size_t)(r0 + row) * 1024 + k0 + c * 8);
    }
}
__device__ __forceinline__ void r_stage(uint32_t sb, int s, int n0, int k0, int tid) {
    uint32_t sa = sb + s * RSTAGE;
#pragma unroll
    for (int p = 0; p < 4; p++) {
        int idx = p * 256 + tid;
        int bufl = idx >> 9;
        int t = idx & 511;
        int row = t >> 3, ch = t & 7;
        const __half* src = bufl ? g_AGl : g_AGh;
        cpasync16(sa + bufl * R_A_BYTES + (uint32_t)(row * RPAD + ch * 8) * 2,
                  src + (size_t)row * 1024 + k0 + ch * 8);
    }
#pragma unroll
    for (int p = 0; p < 4; p++) {
        int idx = p * 256 + tid;
        int row = idx >> 3, ch = idx & 7;
        cpasync16(sa + 2 * R_A_BYTES + (uint32_t)(row * RPAD + ch * 8) * 2,
                  g_Xh + (size_t)(n0 + row) * 1024 + k0 + ch * 8);
    }
}

__global__ __launch_bounds__(256, 2) void k_yzrag() {
    extern __shared__ __align__(16) char ysmem[];
    const uint32_t sb = smem_u32(ysmem);
    const int tid = threadIdx.x, lane = tid & 31, wid = tid >> 5;
    int blk = blockIdx.x;

    if (blk >= 256) {
        // ---- yz: CTA 128x128, warp tile 64x32, 2-stage ----
        int yb = blk - 256;
        const int wm = wid >> 2, wn = wid & 3;
        const int m0 = (yb >> 3) * 128, n0 = (yb & 7) * 128;

        y_stage3(sb, 0, m0, n0, 0, tid);
        CP_COMMIT();

        float d[4][4][4] = {};
        const int aRow = wm * 64 + (lane & 15);
        const int aCol = (lane >> 4) * 8;
        const int bRow = wn * 32 + (lane & 7) + (lane >> 4) * 8;
        const int bCol = ((lane >> 3) & 1) * 8;

        for (int it = 0; it < 16; it++) {
            CP_WAIT(0);
            __syncthreads();
            if (it + 1 < 16) {
                y_stage3(sb, (it + 1) & 1, m0, n0, (it + 1) * 64, tid);
                CP_COMMIT();
            }
            uint32_t abase = sb + (it & 1) * Y3STAGE;
            uint32_t bbase = abase + Y3BUF;
#pragma unroll
            for (int ks = 0; ks < 4; ks++) {
                int kc = ks * 16;
                uint32_t ar[4][4];
#pragma unroll
                for (int i = 0; i < 4; i++)
                    ldsm4(ar[i], abase + (uint32_t)((aRow + i * 16) * Y3PAD + kc + aCol) * 2);
                uint32_t br[2][4];
#pragma unroll
                for (int j = 0; j < 2; j++)
                    ldsm4(br[j], bbase + (uint32_t)((bRow + j * 16) * Y3PAD + kc + bCol) * 2);
#pragma unroll
                for (int i = 0; i < 4; i++)
#pragma unroll
                    for (int j = 0; j < 4; j++)
                        mma_f16(d[i][j], ar[i], br[j >> 1][(j & 1) * 2],
                                br[j >> 1][(j & 1) * 2 + 1]);
            }
        }
        __syncthreads();

        // epilogue: add Bm
        const int grp = lane >> 2, tig = lane & 3;
#pragma unroll
        for (int i = 0; i < 4; i++) {
            int r0 = wm * 64 + i * 16 + grp;
            int p0 = r0 & 31, p1 = (r0 + 8) & 31;
#pragma unroll
            for (int j = 0; j < 4; j++) {
                int cc = n0 + wn * 32 + j * 8 + tig * 2;
                float2 b0 = *(const float2*)(g_Bm + p0 * 1024 + cc);
                float2 b1 = *(const float2*)(g_Bm + p1 * 1024 + cc);
                d[i][j][0] += b0.x; d[i][j][1] += b0.y;
                d[i][j][2] += b1.x; d[i][j][3] += b1.y;
            }
        }

        // issue X tile load (128 rows x 128 f-cols at n0), into ZXH
        const uint32_t ZYH = sb, ZYL = sb + ZBUF3, ZXH = sb + 2 * ZBUF3;
#pragma unroll
        for (int p = 0; p < 8; p++) {
            int idx = p * 256 + tid;       // 0..2047 = 128 rows x 16 chunks
            int row = idx >> 4, ch = idx & 15;
            cpasync16(ZXH + (uint32_t)(row * 136 + ch * 8) * 2,
                      g_Xh + (size_t)(m0 + row) * 1024 + n0 + ch * 8);
        }
        CP_COMMIT();
        // write Y' hi/lo (full 128x128, every warp its own cols)
#pragma unroll
        for (int i = 0; i < 4; i++) {
            int r0 = wm * 64 + i * 16 + grp;
#pragma unroll
            for (int j = 0; j < 4; j++) {
                int cl = wn * 32 + j * 8 + tig * 2;
                float v0 = d[i][j][0], v1 = d[i][j][1];
                float v2 = d[i][j][2], v3 = d[i][j][3];
                __half h0 = __float2half_rn(v0), h1 = __float2half_rn(v1);
                __half h2 = __float2half_rn(v2), h3 = __float2half_rn(v3);
                *(__half2*)(ysmem + ((r0) * 136 + cl) * 2) = __halves2half2(h0, h1);
                *(__half2*)(ysmem + ((r0 + 8) * 136 + cl) * 2) = __halves2half2(h2, h3);
                *(__half2*)(ysmem + ZBUF3 + ((r0) * 136 + cl) * 2) =
                    __halves2half2(__float2half_rn(v0 - __half2float(h0)),
                                   __float2half_rn(v1 - __half2float(h1)));
                *(__half2*)(ysmem + ZBUF3 + ((r0 + 8) * 136 + cl) * 2) =
                    __halves2half2(__float2half_rn(v2 - __half2float(h2)),
                                   __float2half_rn(v3 - __half2float(h3)));
            }
        }
        CP_WAIT(0);
        __syncthreads();

        // Z mma: 8 warps = 4 batches x 2 n-halves; k = 128 (this block's f-cols)
        const int bb = wid >> 1;
        const int nh = wid & 1;
        float z[2][2][4] = {};
#pragma unroll
        for (int ksl = 0; ksl < 8; ksl++) {
            int kc = ksl * 16;
            uint32_t ayh[2][4], ayl[2][4];
#pragma unroll
            for (int mi = 0; mi < 2; mi++) {
                uint32_t ao = (uint32_t)((bb * 32 + mi * 16 + (lane & 15)) * 136 +
                                         kc + (lane >> 4) * 8) * 2;
                ldsm4(ayh[mi], ZYH + ao);
                ldsm4(ayl[mi], ZYL + ao);
            }
            uint32_t bxh[4];
            uint32_t bo = (uint32_t)((bb * 32 + nh * 16 + (lane & 7) + (lane >> 4) * 8) * 136 +
                                     kc + ((lane >> 3) & 1) * 8) * 2;
            ldsm4(bxh, ZXH + bo);
#pragma unroll
            for (int mi = 0; mi < 2; mi++)
#pragma unroll
                for (int no = 0; no < 2; no++) {
                    mma_f16(z[mi][no], ayh[mi], bxh[no * 2], bxh[no * 2 + 1]);
                    mma_f16(z[mi][no], ayl[mi], bxh[no * 2], bxh[no * 2 + 1]);
                }
        }
        // store Z partials: slot = n-block (8 slots)
        {
            int b = (yb >> 3) * 4 + bb;
            size_t base = ((size_t)(yb & 7) * 1024 + b) * 1024;
#pragma unroll
            for (int mi = 0; mi < 2; mi++) {
                int i0 = mi * 16 + grp;
#pragma unroll
                for (int no = 0; no < 2; no++) {
                    int j0 = nh * 16 + no * 8 + tig * 2;
                    *(float2*)(g_Zpart + base + i0 * 32 + j0) =
                        make_float2(z[mi][no][0], z[mi][no][1]);
                    *(float2*)(g_Zpart + base + (i0 + 8) * 32 + j0) =
                        make_float2(z[mi][no][2], z[mi][no][3]);
                }
            }
        }
    } else {
        // ---- rag: [A;G] @ Xall^T (2-product), n-tile 128, scheduled in wave 1 ----
        const int wm = wid >> 2, wn = wid & 3;
        const int n0 = blk * 128;

        r_stage(sb, 0, n0, 0, tid);
        CP_COMMIT();

        float d[2][2][2][4] = {};
        const int aRowB = wm * 32 + (lane & 15);
        const int aCol = (lane >> 4) * 8;
        const int bRowB = wn * 32 + (lane & 7) + (lane >> 4) * 8;
        const int bCol = ((lane >> 3) & 1) * 8;

        for (int it = 0; it < 16; it++) {
            CP_WAIT(0);
            __syncthreads();
            if (it + 1 < 16) {
                r_stage(sb, (it + 1) & 1, n0, (it + 1) * 64, tid);
                CP_COMMIT();
            }
            uint32_t st = sb + (it & 1) * RSTAGE;
            uint32_t sB = st + 2 * R_A_BYTES;
#pragma unroll
            for (int ks = 0; ks < 4; ks++) {
                int kc = ks * 16;
                uint32_t ah[2][4], al[2][4];
#pragma unroll
                for (int mi = 0; mi < 2; mi++) {
                    uint32_t ao = (uint32_t)((aRowB + mi * 16) * RPAD + kc + aCol) * 2;
                    ldsm4(ah[mi], st + ao);
                    ldsm4(al[mi], st + R_A_BYTES + ao);
                }
                uint32_t bh[2][4];
#pragma unroll
                for (int nj = 0; nj < 2; nj++) {
                    uint32_t bo = (uint32_t)((bRowB + nj * 16) * RPAD + kc + bCol) * 2;
                    ldsm4(bh[nj], sB + bo);
                }
#pragma unroll
                for (int mi = 0; mi < 2; mi++)
#pragma unroll
                    for (int nj = 0; nj < 2; nj++)
#pragma unroll
                        for (int s = 0; s < 2; s++) {
                            mma_f16(d[mi][nj][s], ah[mi], bh[nj][s * 2], bh[nj][s * 2 + 1]);
                            mma_f16(d[mi][nj][s], al[mi], bh[nj][s * 2], bh[nj][s * 2 + 1]);
                        }
            }
        }
        const int grp = lane >> 2, tig = lane & 3;
#pragma unroll
        for (int mi = 0; mi < 2; mi++) {
            int r0 = wm * 32 + mi * 16 + grp, r1 = r0 + 8;
#pragma unroll
            for (int nj = 0; nj < 2; nj++)
#pragma unroll
                for (int s = 0; s < 2; s++) {
                    int col = n0 + wn * 32 + nj * 16 + s * 8 + tig * 2;
                    *(float2*)(g_RAG + (size_t)r0 * 32768 + col) =
                        make_float2(d[mi][nj][s][0], d[mi][nj][s][1]);
                    *(float2*)(g_RAG + (size_t)r1 * 32768 + col) =
                        make_float2(d[mi][nj][s][2], d[mi][nj][s][3]);
                }
        }
    }
}

// ----- kernel 7: reduce Z partials (8 slots) + softmax(dim=1) + final dot -----
__global__ __launch_bounds__(256) void k_attn2(const float* __restrict__ bfc,
                                               float* __restrict__ out) {
    __shared__ float Zs[32 * 33];
    __shared__ float As[32 * 33];
    __shared__ float Vs[32 * 33];
    __shared__ float wpart[8];
    int tid = threadIdx.x, b = blockIdx.x;
#pragma unroll
    for (int p = 0; p < 4; p++) {
        int idx = p * 256 + tid;
        int i = idx >> 5, j = idx & 31;
        float s = 0.f;
#pragma unroll
        for (int nb = 0; nb < 8; nb++)
            s += g_Zpart[((size_t)nb * 1024 + b) * 1024 + idx];
        Zs[i * 33 + j] = s;
        As[i * 33 + j] = g_RAG[(size_t)j * 32768 + b * 32 + i];
        Vs[i * 33 + j] = g_RAG[(size_t)(32 + i) * 32768 + b * 32 + j];
    }
    __syncthreads();
    int w = tid >> 5, lane = tid & 31;
    const float rscale = 0.022097086912079608f;  // 1/sqrt(2048)
    float local = 0.f;
#pragma unroll
    for (int q = 0; q < 4; q++) {
        int j = w * 4 + q;
        float lg = (Zs[lane * 33 + j] + As[lane * 33 + j] + g_c[lane * 32 + j]) * rscale;
        float mx = wredmax(lg);
        float ex = __expf(lg - mx);
        float sm = wredsum(ex);
        float contrib = (ex / sm) * (Vs[lane * 33 + j] + g_P[lane * 32 + j]);
        local += wredsum(contrib);
    }
    if (lane == 0) wpart[w] = local;
    __syncthreads();
    if (tid == 0) {
        float t = 0.f;
#pragma unroll
        for (int i = 0; i < 8; i++) t += wpart[i];
        out[b] = t + bfc[0];
    }
}

extern "C" void kernel_launch(void* const* d_in, const int* in_sizes, int n_in,
                              void* d_out, int out_size) {
    const float* x   = (const float*)d_in[0];
    const float* pe  = (const float*)d_in[1];
    const float* Wq  = (const float*)d_in[2];
    const float* bq  = (const float*)d_in[3];
    const float* Wk  = (const float*)d_in[4];
    const float* bk  = (const float*)d_in[5];
    const float* Wv  = (const float*)d_in[6];
    const float* bv  = (const float*)d_in[7];
    const float* Wfc = (const float*)d_in[8];
    const float* bfc = (const float*)d_in[9];
    float* out = (float*)d_out;

    cudaFuncSetAttribute(k_gs, cudaFuncAttributeMaxDynamicSharedMemorySize, GSMEM);
    cudaFuncSetAttribute(k_yzrag, cudaFuncAttributeMaxDynamicSharedMemorySize, YSMEM3);

    k_prep<<<39744, 256>>>(x, pe, Wq, bq, Wk, bk, Wv, bv, Wfc);
    k_gs<<<448, 256, GSMEM>>>();
    k_mid<<<1472, 256>>>(Wfc);
    k_yzrag<<<2304, 256, YSMEM3>>>();
    k_attn2<<<1024, 256>>>(bfc, out);
}